// round 1
// baseline (speedup 1.0000x reference)
#include <cuda_runtime.h>

#define Np 1024
#define HW 4096

// ---------------- scratch (static device arrays; no runtime allocation) ---
__device__ float    g_rowsum[(size_t)HW * HW];   // 64 MB: inclusive row cumsum
__device__ float    g_scores[Np];
__device__ float    g_scores_s[Np];
__device__ float    g_bbox_s[Np * 4];
__device__ unsigned g_iou[Np * 32];              // bitmask: IoU > 0.5 on sorted boxes
__device__ float    g_rec_score[Np];
__device__ int      g_rec_flag[Np];
__device__ unsigned g_rec_sel[Np * 32];

// ---------------- K1: per-row inclusive cumsum of probs -------------------
// One thread per row, float4 vectorized. Row magnitudes <= ~2048 so f32
// accumulation error is negligible for the downstream box sums.
__global__ void k_rowcumsum(const float4* __restrict__ p) {
    int r = blockIdx.x * blockDim.x + threadIdx.x;
    if (r >= HW) return;
    const float4* pr   = p + (size_t)r * (HW / 4);
    float4*       orow = reinterpret_cast<float4*>(g_rowsum) + (size_t)r * (HW / 4);
    float acc = 0.f;
#pragma unroll 4
    for (int c = 0; c < HW / 4; c++) {
        float4 v = pr[c];
        float4 o;
        o.x = acc + v.x;
        o.y = o.x + v.y;
        o.z = o.y + v.z;
        o.w = o.z + v.w;
        acc = o.w;
        orow[c] = o;
    }
}

// ---------------- K2: per-box mean + combined score ------------------------
// One warp per box; lanes stride rows; double accumulation of row-sum diffs.
__global__ void k_boxscore(const float* __restrict__ bbox,
                           const float* __restrict__ obj) {
    int gw   = (blockIdx.x * blockDim.x + threadIdx.x) >> 5;
    int lane = threadIdx.x & 31;
    if (gw >= Np) return;
    float4 b = reinterpret_cast<const float4*>(bbox)[gw];
    int x1 = min(max((int)floorf(b.x), 0), HW);
    int y1 = min(max((int)floorf(b.y), 0), HW);
    int x2 = min(max((int)floorf(b.z), 0), HW);
    int y2 = min(max((int)floorf(b.w), 0), HW);
    double s = 0.0;
    for (int y = y1 + lane; y < y2; y += 32) {
        const float* row = g_rowsum + (size_t)y * HW;
        float right = (x2 > 0) ? row[x2 - 1] : 0.f;
        float left  = (x1 > 0) ? row[x1 - 1] : 0.f;
        s += (double)(right - left);
    }
#pragma unroll
    for (int o = 16; o > 0; o >>= 1) s += __shfl_down_sync(0xffffffffu, s, o);
    if (lane == 0) {
        long long cnt = (long long)(y2 - y1) * (long long)(x2 - x1);
        if (cnt < 1) cnt = 1;
        float bs = (float)(s / (double)cnt);
        g_scores[gw] = 0.5f * (obj[gw] + bs);
    }
}

// ---------------- K3: bitonic sort (desc score, ties asc index == stable) --
__global__ void k_sort(const float* __restrict__ bbox) {
    __shared__ float sk[Np];
    __shared__ int   si[Np];
    int t = threadIdx.x;
    sk[t] = g_scores[t];
    si[t] = t;
    __syncthreads();
    for (int size = 2; size <= Np; size <<= 1) {
        for (int stride = size >> 1; stride > 0; stride >>= 1) {
            int p = t ^ stride;
            if (p > t) {
                float ka = sk[t], kb = sk[p];
                int   ia = si[t], ib = si[p];
                // "a after b" in desired final order (desc score, asc idx on ties)
                bool a_after_b = (ka < kb) || (ka == kb && ia > ib);
                bool upSeg = ((t & size) == 0);
                bool doswap = upSeg ? a_after_b : !a_after_b;
                if (doswap) { sk[t] = kb; sk[p] = ka; si[t] = ib; si[p] = ia; }
            }
            __syncthreads();
        }
    }
    g_scores_s[t] = sk[t];
    int o = si[t];
    reinterpret_cast<float4*>(g_bbox_s)[t] =
        reinterpret_cast<const float4*>(bbox)[o];
}

// ---------------- K4: IoU > 0.5 bitmask on sorted boxes --------------------
__global__ void k_iou() {
    __shared__ float4 sb[Np];
    int i = blockIdx.x;
    int t = threadIdx.x;  // 32 threads
    for (int k = t; k < Np; k += 32)
        sb[k] = reinterpret_cast<const float4*>(g_bbox_s)[k];
    __syncthreads();
    float4 a = sb[i];
    float aarea = (a.z - a.x) * (a.w - a.y);
    unsigned m = 0;
#pragma unroll 8
    for (int bI = 0; bI < 32; bI++) {
        int j = t * 32 + bI;
        float4 c = sb[j];
        float carea = (c.z - c.x) * (c.w - c.y);
        float ix1 = fmaxf(a.x, c.x), iy1 = fmaxf(a.y, c.y);
        float ix2 = fminf(a.z, c.z), iy2 = fminf(a.w, c.w);
        float iw = fmaxf(ix2 - ix1, 0.f), ih = fmaxf(iy2 - iy1, 0.f);
        float inter = iw * ih;
        float iou = inter / (aarea + carea - inter);
        if (iou > 0.5f) m |= (1u << bI);
    }
    g_iou[i * 32 + t] = m;
}

// ---------------- K5: c_wsl greedy sweep — one warp per start --------------
// Lane k holds selection-mask word k. check-before-add semantics: record
// happens at the TOP of iteration j, so a group completed at j=N-1 is never
// recorded (matches the reference scan). Score accumulated in f32 in the
// same order as the reference.
__global__ void k_cwsl(const int* __restrict__ counts_p) {
    int gw   = (blockIdx.x * blockDim.x + threadIdx.x) >> 5;
    int lane = threadIdx.x & 31;
    if (gw >= Np) return;
    int counts = counts_p[0];
    int i = gw;
    unsigned sel = (lane == (i >> 5)) ? (1u << (i & 31)) : 0u;
    int   size  = 1;
    float score = g_scores_s[i];
    bool  rec   = false;
    unsigned row = (i + 1 < Np) ? g_iou[(i + 1) * 32 + lane] : 0u;
    for (int j = i + 1; j < Np; j++) {
        unsigned nxt = (j + 1 < Np) ? g_iou[(j + 1) * 32 + lane] : 0u;
        if (size == counts) { rec = true; break; }
        bool overlap = __any_sync(0xffffffffu, (sel & row) != 0u);
        if (!overlap) {
            if (lane == (j >> 5)) sel |= (1u << (j & 31));
            size++;
            score += g_scores_s[j];
        }
        row = nxt;
    }
    g_rec_sel[i * 32 + lane] = sel;
    if (lane == 0) {
        g_rec_flag[i]  = rec ? 1 : 0;
        g_rec_score[i] = rec ? score : -1e30f;
    }
}

// ---------------- K6: last-argmax over recorded scores + emit output -------
__global__ void k_final(float* __restrict__ out) {
    __shared__ float ss[Np];
    __shared__ int   si[Np];
    int t = threadIdx.x;
    ss[t] = g_rec_score[t];  // already -1e30 when not recorded
    si[t] = t;
    __syncthreads();
    for (int s = Np / 2; s > 0; s >>= 1) {
        if (t < s) {
            float o = ss[t + s]; int oi = si[t + s];
            // prefer larger score; on exact tie prefer larger index (last argmax)
            if (o > ss[t] || (o == ss[t] && oi > si[t])) { ss[t] = o; si[t] = oi; }
        }
        __syncthreads();
    }
    __shared__ int bestIdx, anyrec;
    if (t == 0) { bestIdx = si[0]; anyrec = (ss[0] > -1e29f) ? 1 : 0; }
    __syncthreads();
    unsigned bit = (g_rec_sel[bestIdx * 32 + (t >> 5)] >> (t & 31)) & 1u;
    out[t] = (anyrec && bit) ? g_scores_s[t] : 0.f;
}

// ---------------- launch ----------------------------------------------------
extern "C" void kernel_launch(void* const* d_in, const int* in_sizes, int n_in,
                              void* d_out, int out_size) {
    const float* bbox   = (const float*)d_in[0];
    const float* obj    = (const float*)d_in[1];
    const float* probs  = (const float*)d_in[2];
    const int*   counts = (const int*)d_in[3];
    float* out = (float*)d_out;

    k_rowcumsum<<<(HW + 255) / 256, 256>>>((const float4*)probs);
    k_boxscore<<<(Np * 32) / 256, 256>>>(bbox, obj);
    k_sort<<<1, Np>>>(bbox);
    k_iou<<<Np, 32>>>();
    k_cwsl<<<(Np * 32) / 256, 256>>>(counts);
    k_final<<<1, Np>>>(out);
}

// round 2
// speedup vs baseline: 5.3078x; 5.3078x over previous
#include <cuda_runtime.h>

#define Np 1024
#define HW 4096

// ---------------- scratch (static device arrays; no runtime allocation) ---
__device__ float    g_rowsum[(size_t)HW * HW];   // 64 MB: inclusive row cumsum
__device__ float    g_scores[Np];
__device__ float    g_scores_s[Np];
__device__ float    g_bbox_s[Np * 4];
__device__ unsigned g_iou[Np * 32];              // bitmask: IoU > 0.5 on sorted boxes
__device__ float    g_rec_score[Np];
__device__ unsigned g_rec_sel[Np * 32];

// ---------------- K1: per-row inclusive cumsum of probs -------------------
// ONE WARP PER ROW. Each chunk = 128 floats (float4/lane); local scan in
// registers, 5-step shuffle scan across lanes, carry propagated serially
// across 32 chunks. 4096 warps -> memory-bound (~128 MB total traffic).
__global__ void k_rowcumsum(const float4* __restrict__ p) {
    int gw   = (blockIdx.x * blockDim.x + threadIdx.x) >> 5;  // row
    int lane = threadIdx.x & 31;
    if (gw >= HW) return;
    const float4* pr   = p + (size_t)gw * (HW / 4);
    float4*       orow = reinterpret_cast<float4*>(g_rowsum) + (size_t)gw * (HW / 4);
    float carry = 0.f;
#pragma unroll 4
    for (int c = 0; c < HW / 4; c += 32) {
        float4 v = pr[c + lane];
        // local inclusive scan of the 4 elements
        v.y += v.x; v.z += v.y; v.w += v.z;
        float s = v.w;
        // inclusive warp scan of per-lane totals
        float t = s;
#pragma unroll
        for (int o = 1; o < 32; o <<= 1) {
            float u = __shfl_up_sync(0xffffffffu, t, o);
            if (lane >= o) t += u;
        }
        float excl = carry + (t - s);
        v.x += excl; v.y += excl; v.z += excl; v.w += excl;
        orow[c + lane] = v;
        carry += __shfl_sync(0xffffffffu, t, 31);
    }
}

// ---------------- K2: per-box mean + combined score ------------------------
// One warp per box; lanes stride rows; double accumulation of row-sum diffs.
__global__ void k_boxscore(const float* __restrict__ bbox,
                           const float* __restrict__ obj) {
    int gw   = (blockIdx.x * blockDim.x + threadIdx.x) >> 5;
    int lane = threadIdx.x & 31;
    if (gw >= Np) return;
    float4 b = reinterpret_cast<const float4*>(bbox)[gw];
    int x1 = min(max((int)floorf(b.x), 0), HW);
    int y1 = min(max((int)floorf(b.y), 0), HW);
    int x2 = min(max((int)floorf(b.z), 0), HW);
    int y2 = min(max((int)floorf(b.w), 0), HW);
    double s = 0.0;
    for (int y = y1 + lane; y < y2; y += 32) {
        const float* row = g_rowsum + (size_t)y * HW;
        float right = (x2 > 0) ? __ldg(row + x2 - 1) : 0.f;
        float left  = (x1 > 0) ? __ldg(row + x1 - 1) : 0.f;
        s += (double)(right - left);
    }
#pragma unroll
    for (int o = 16; o > 0; o >>= 1) s += __shfl_down_sync(0xffffffffu, s, o);
    if (lane == 0) {
        long long cnt = (long long)(y2 - y1) * (long long)(x2 - x1);
        if (cnt < 1) cnt = 1;
        float bs = (float)(s / (double)cnt);
        g_scores[gw] = 0.5f * (obj[gw] + bs);
    }
}

// ---------------- K3: bitonic sort (desc score, ties asc index == stable) --
__global__ void k_sort(const float* __restrict__ bbox) {
    __shared__ float sk[Np];
    __shared__ int   si[Np];
    int t = threadIdx.x;
    sk[t] = g_scores[t];
    si[t] = t;
    __syncthreads();
    for (int size = 2; size <= Np; size <<= 1) {
        for (int stride = size >> 1; stride > 0; stride >>= 1) {
            int p = t ^ stride;
            if (p > t) {
                float ka = sk[t], kb = sk[p];
                int   ia = si[t], ib = si[p];
                bool a_after_b = (ka < kb) || (ka == kb && ia > ib);
                bool upSeg = ((t & size) == 0);
                bool doswap = upSeg ? a_after_b : !a_after_b;
                if (doswap) { sk[t] = kb; sk[p] = ka; si[t] = ib; si[p] = ia; }
            }
            __syncthreads();
        }
    }
    g_scores_s[t] = sk[t];
    int o = si[t];
    reinterpret_cast<float4*>(g_bbox_s)[t] =
        reinterpret_cast<const float4*>(bbox)[o];
}

// ---------------- K4: IoU > 0.5 bitmask on sorted boxes --------------------
// 8 warps/block: box tile loaded to smem once per 8 output rows.
__global__ void k_iou() {
    __shared__ float4 sb[Np];
    int t = threadIdx.x;               // 256
    for (int k = t; k < Np; k += 256)
        sb[k] = reinterpret_cast<const float4*>(g_bbox_s)[k];
    __syncthreads();
    int wid = t >> 5, lane = t & 31;
    int i = blockIdx.x * 8 + wid;
    float4 a = sb[i];
    float aarea = (a.z - a.x) * (a.w - a.y);
    unsigned m = 0;
#pragma unroll 8
    for (int bI = 0; bI < 32; bI++) {
        int j = lane * 32 + bI;
        float4 c = sb[j];
        float carea = (c.z - c.x) * (c.w - c.y);
        float ix1 = fmaxf(a.x, c.x), iy1 = fmaxf(a.y, c.y);
        float ix2 = fminf(a.z, c.z), iy2 = fminf(a.w, c.w);
        float iw = fmaxf(ix2 - ix1, 0.f), ih = fmaxf(iy2 - iy1, 0.f);
        float inter = iw * ih;
        float iou = inter / (aarea + carea - inter);
        if (iou > 0.5f) m |= (1u << bI);
    }
    g_iou[i * 32 + lane] = m;
}

// ---------------- K5: c_wsl greedy sweep — one warp per start --------------
__global__ void k_cwsl(const int* __restrict__ counts_p) {
    int gw   = (blockIdx.x * blockDim.x + threadIdx.x) >> 5;
    int lane = threadIdx.x & 31;
    if (gw >= Np) return;
    int counts = counts_p[0];
    int i = gw;
    unsigned sel = (lane == (i >> 5)) ? (1u << (i & 31)) : 0u;
    int   size  = 1;
    float score = g_scores_s[i];
    bool  rec   = false;
    unsigned row = (i + 1 < Np) ? g_iou[(i + 1) * 32 + lane] : 0u;
    for (int j = i + 1; j < Np; j++) {
        unsigned nxt = (j + 1 < Np) ? g_iou[(j + 1) * 32 + lane] : 0u;
        if (size == counts) { rec = true; break; }
        bool overlap = __any_sync(0xffffffffu, (sel & row) != 0u);
        if (!overlap) {
            if (lane == (j >> 5)) sel |= (1u << (j & 31));
            size++;
            score += g_scores_s[j];
        }
        row = nxt;
    }
    g_rec_sel[i * 32 + lane] = sel;
    if (lane == 0) g_rec_score[i] = rec ? score : -1e30f;
}

// ---------------- K6: last-argmax over recorded scores + emit output -------
__global__ void k_final(float* __restrict__ out) {
    __shared__ float ss[Np];
    __shared__ int   si[Np];
    int t = threadIdx.x;
    ss[t] = g_rec_score[t];  // -1e30 when not recorded
    si[t] = t;
    __syncthreads();
    for (int s = Np / 2; s > 0; s >>= 1) {
        if (t < s) {
            float o = ss[t + s]; int oi = si[t + s];
            if (o > ss[t] || (o == ss[t] && oi > si[t])) { ss[t] = o; si[t] = oi; }
        }
        __syncthreads();
    }
    __shared__ int bestIdx, anyrec;
    if (t == 0) { bestIdx = si[0]; anyrec = (ss[0] > -1e29f) ? 1 : 0; }
    __syncthreads();
    unsigned bit = (g_rec_sel[bestIdx * 32 + (t >> 5)] >> (t & 31)) & 1u;
    out[t] = (anyrec && bit) ? g_scores_s[t] : 0.f;
}

// ---------------- launch ----------------------------------------------------
extern "C" void kernel_launch(void* const* d_in, const int* in_sizes, int n_in,
                              void* d_out, int out_size) {
    const float* bbox   = (const float*)d_in[0];
    const float* obj    = (const float*)d_in[1];
    const float* probs  = (const float*)d_in[2];
    const int*   counts = (const int*)d_in[3];
    float* out = (float*)d_out;

    k_rowcumsum<<<(HW * 32 + 255) / 256, 256>>>((const float4*)probs);
    k_boxscore<<<(Np * 32) / 256, 256>>>(bbox, obj);
    k_sort<<<1, Np>>>(bbox);
    k_iou<<<Np / 8, 256>>>();
    k_cwsl<<<(Np * 32) / 256, 256>>>(counts);
    k_final<<<1, Np>>>(out);
}